// round 12
// baseline (speedup 1.0000x reference)
#include <cuda_runtime.h>
#include <math.h>

#define BB 4096
#define DD 2048
#define KK 8
#define PCOLS 25   // 3K+1

constexpr float RMIN = -5.0f;
constexpr float RMAX = 5.0f;
constexpr float MIN_BIN = 1e-3f;
constexpr float MIN_SLOPE = 1e-3f;
constexpr float MAX_SLOPE = 10.0f;

// Packed main table: [9][DD] of float4 {y_k, h, 1/w, slope_j}; row 8 = {0,0,0,slope_8}.
__device__ float4 g_main[9 * DD];
// Interior knots x_k[1..7], SoA [7][DD].
__device__ float  g_knots[7 * DD];
// Per-bin xi-intercept: c_j = -x_knot_j / w_j, SoA [8][DD].
__device__ float  g_c[8 * DD];

// Warp-per-d normalization: lane j holds param j (j<25).
__global__ void __launch_bounds__(256) norm_kernel(const float* __restrict__ params,
                                                   float* __restrict__ ld_out) {
    const int lane = threadIdx.x & 31;
    const int d = (blockIdx.x * blockDim.x + threadIdx.x) >> 5;

    const float* p = params + (size_t)d * PCOLS;
    const float raw = (lane < PCOLS) ? p[lane] : 0.f;
    const float sig = 1.f / (1.f + __expf(-raw));

    float gs = sig;
    gs += __shfl_xor_sync(0xffffffffu, gs, 4);
    gs += __shfl_xor_sync(0xffffffffu, gs, 2);
    gs += __shfl_xor_sync(0xffffffffu, gs, 1);

    const float rem = (RMAX - RMIN) - KK * MIN_BIN;
    const float val = MIN_BIN + sig * (rem / gs);
    const float slope = MIN_SLOPE + sig * (MAX_SLOPE - MIN_SLOPE);

    float scan = val;
    float t;
    t = __shfl_up_sync(0xffffffffu, scan, 1); if ((lane & 7) >= 1) scan += t;
    t = __shfl_up_sync(0xffffffffu, scan, 2); if ((lane & 7) >= 2) scan += t;
    t = __shfl_up_sync(0xffffffffu, scan, 4); if ((lane & 7) >= 4) scan += t;

    const int j = lane & 7;
    const float ht     = __shfl_sync(0xffffffffu, val,   8 + j);
    const float ht_inc = __shfl_sync(0xffffffffu, scan,  8 + j);
    const float sl_j   = __shfl_sync(0xffffffffu, slope, 16 + j);
    const float sl_8   = __shfl_sync(0xffffffffu, slope, 24);

    if (lane < 8) {
        const float rw = 1.f / val;
        const float lo = RMIN + scan - val;         // x_knot_j
        float4 v;
        v.x = RMIN + ht_inc - ht;                   // y_k
        v.y = ht;
        v.z = rw;
        v.w = sl_j;
        g_main[lane * DD + d] = v;
        g_c[lane * DD + d] = -lo * rw;              // xi = fma(xc, rw, c)
        if (lane < 7) g_knots[lane * DD + d] = RMIN + scan;
    }
    if (lane == 8) g_main[8 * DD + d] = make_float4(0.f, 0.f, 0.f, sl_8);

    const int g = blockIdx.x * blockDim.x + threadIdx.x;
    if (g < BB) ld_out[g] = 0.f;
}

#define DT 128        // threads per CTA; each owns 2 columns (tid, tid+128)
#define COLS 256      // columns per CTA
#define NCHUNK 512    // total row-chunks of 8 (BB/8)
#define GY 64         // 8 x-groups * 64 = 512 CTAs, all resident, 8 chunks each

struct YD { float y, dv; };

__device__ __forceinline__ YD eval_one(float xv, const float vk[7],
                                       const float4* __restrict__ sm4,
                                       const float*  __restrict__ smc,
                                       int col) {
    const float xc = fminf(fmaxf(xv, RMIN), RMAX);

    int bin = 0;
    if (xc >= vk[3]) bin = 4;
    const float c2 = (bin & 4) ? vk[5] : vk[1];
    if (xc >= c2) bin += 2;
    const float c1 = (bin & 4) ? ((bin & 2) ? vk[6] : vk[4])
                               : ((bin & 2) ? vk[2] : vk[0]);
    if (xc >= c1) bin += 1;

    const int idx = bin * COLS + col;
    const float4 t = sm4[idx];          // {y_k, h, rw, dk}
    const float dk1 = (&sm4[idx])[COLS].w;
    const float cc  = smc[idx];

    const float s   = t.y * t.z;
    const float xi  = fmaf(xc, t.z, cc);
    const float sd  = s - t.w;
    const float A   = (dk1 - s) - sd;

    const float ni  = fmaf(xi, sd, t.w);
    const float t1  = fmaf(A, -xi, A);
    const float den = fmaf(xi, t1, s);
    const float rden = __fdividef(1.f, den);

    const float di = fmaf(fmaf(A, xi, sd + sd), xi, t.w);
    const float sr = s * rden;

    YD out;
    out.dv = di * sr * sr;              // raw derivative (log deferred to reduction)

    float yv = fmaf(t.y * xi * ni, rden, t.x);
    const float tail = xv - xc;         // 0 in-range; exact linear extension otherwise
    out.y = fmaf(tail, (xv < 0.f) ? t.w : dk1, yv);
    return out;
}

__global__ void __launch_bounds__(DT, 5) eval_kernel(const float* __restrict__ x,
                                                     float* __restrict__ y,
                                                     float* __restrict__ ld_out) {
    __shared__ float4 sm4[9 * COLS];   // 36.9 KB
    __shared__ float  smc[8 * COLS];   //  8 KB   (total 44.9 KB; 5 CTAs/SM)

    const int tid = threadIdx.x;
    const int lane = tid & 31;
    const int d0 = blockIdx.x * COLS + tid;        // column A
    const int d1 = d0 + 128;                       // column B

#pragma unroll
    for (int j = 0; j < 9; j++) {
        sm4[j * COLS + tid]       = g_main[j * DD + d0];
        sm4[j * COLS + tid + 128] = g_main[j * DD + d1];
    }
#pragma unroll
    for (int j = 0; j < 8; j++) {
        smc[j * COLS + tid]       = g_c[j * DD + d0];
        smc[j * COLS + tid + 128] = g_c[j * DD + d1];
    }

    float vkA[7], vkB[7];
#pragma unroll
    for (int j = 0; j < 7; j++) {
        vkA[j] = g_knots[j * DD + d0];
        vkB[j] = g_knots[j * DD + d1];
    }
    __syncthreads();

    // lane-dependent constants for the transpose reduction
    const bool k4 = (lane & 16) != 0;
    const bool k2 = (lane & 8)  != 0;
    const bool k1 = (lane & 4)  != 0;
    const int  red_row = ((lane >> 4) & 1) * 4 + ((lane >> 3) & 1) * 2 + ((lane >> 2) & 1);

#pragma unroll 1
    for (int c = blockIdx.y; c < NCHUNK; c += GY) {
        const int b0 = c * 8;
        const float* xp = x + (size_t)b0 * DD + d0;
        float*       yp = y + (size_t)b0 * DD + d0;

        float prod[8];

        // ---- column A ----
        {
            float xin[8];
#pragma unroll
            for (int r = 0; r < 8; r++) xin[r] = __ldg(&xp[r * DD]);
#pragma unroll
            for (int r = 0; r < 8; r++) {
                const YD e = eval_one(xin[r], vkA, sm4, smc, tid);
                yp[r * DD] = e.y;
                prod[r] = e.dv;
            }
        }
        // ---- column B ----
        {
            float xin[8];
#pragma unroll
            for (int r = 0; r < 8; r++) xin[r] = __ldg(&xp[r * DD + 128]);
#pragma unroll
            for (int r = 0; r < 8; r++) {
                const YD e = eval_one(xin[r], vkB, sm4, smc, tid + 128);
                yp[r * DD + 128] = e.y;
                prod[r] *= e.dv;
            }
        }

        // Transpose-reduce: stages 1-3 MULTIPLY derivative products, then one log,
        // then stages 4-5 ADD logs.
        float w4[4];
#pragma unroll
        for (int i = 0; i < 4; i++) {
            const float keep = k4 ? prod[i + 4] : prod[i];
            const float send = k4 ? prod[i] : prod[i + 4];
            w4[i] = keep * __shfl_xor_sync(0xffffffffu, send, 16);
        }
        float w2[2];
#pragma unroll
        for (int i = 0; i < 2; i++) {
            const float keep = k2 ? w4[i + 2] : w4[i];
            const float send = k2 ? w4[i] : w4[i + 2];
            w2[i] = keep * __shfl_xor_sync(0xffffffffu, send, 8);
        }
        const float pz = (k1 ? w2[1] : w2[0]) * __shfl_xor_sync(0xffffffffu, k1 ? w2[0] : w2[1], 4);

        float z = __logf(pz);           // one log per 16 elements
        z += __shfl_xor_sync(0xffffffffu, z, 2);
        z += __shfl_xor_sync(0xffffffffu, z, 1);

        if ((lane & 3) == 0) atomicAdd(&ld_out[b0 + red_row], z);
    }
}

extern "C" void kernel_launch(void* const* d_in, const int* in_sizes, int n_in,
                              void* d_out, int out_size) {
    const float* x;
    const float* params;
    if (in_sizes[0] == BB * DD) { x = (const float*)d_in[0]; params = (const float*)d_in[1]; }
    else                        { x = (const float*)d_in[1]; params = (const float*)d_in[0]; }

    float* y_out  = (float*)d_out;              // [B, D]
    float* ld_out = y_out + (size_t)BB * DD;    // [B]

    static bool configured = false;
    if (!configured) {
        cudaFuncSetAttribute(eval_kernel, cudaFuncAttributePreferredSharedMemoryCarveout, 100);
        configured = true;
    }

    norm_kernel<<<(DD * 32) / 256, 256>>>(params, ld_out);   // warp-per-d
    dim3 grid(DD / COLS, GY);
    eval_kernel<<<grid, DT>>>(x, y_out, ld_out);
}

// round 13
// speedup vs baseline: 1.0932x; 1.0932x over previous
#include <cuda_runtime.h>
#include <math.h>

#define BB 4096
#define DD 2048
#define KK 8
#define PCOLS 25   // 3K+1

constexpr float RMIN = -5.0f;
constexpr float RMAX = 5.0f;
constexpr float MIN_BIN = 1e-3f;
constexpr float MIN_SLOPE = 1e-3f;
constexpr float MAX_SLOPE = 10.0f;

// Packed main table: [9][DD] of float4 {y_k, h, 1/w, slope_j}; row 8 = {0,0,0,slope_8}.
__device__ float4 g_main[9 * DD];
// Interior knots x_k[1..7], SoA [7][DD].
__device__ float  g_knots[7 * DD];
// Per-bin xi-intercept: c_j = -x_knot_j / w_j, SoA [8][DD].
__device__ float  g_c[8 * DD];

// Warp-per-d normalization: lane j holds param j (j<25).
__global__ void __launch_bounds__(256) norm_kernel(const float* __restrict__ params,
                                                   float* __restrict__ ld_out) {
    const int lane = threadIdx.x & 31;
    const int d = (blockIdx.x * blockDim.x + threadIdx.x) >> 5;

    const float* p = params + (size_t)d * PCOLS;
    const float raw = (lane < PCOLS) ? p[lane] : 0.f;
    const float sig = 1.f / (1.f + __expf(-raw));

    float gs = sig;
    gs += __shfl_xor_sync(0xffffffffu, gs, 4);
    gs += __shfl_xor_sync(0xffffffffu, gs, 2);
    gs += __shfl_xor_sync(0xffffffffu, gs, 1);

    const float rem = (RMAX - RMIN) - KK * MIN_BIN;
    const float val = MIN_BIN + sig * (rem / gs);
    const float slope = MIN_SLOPE + sig * (MAX_SLOPE - MIN_SLOPE);

    float scan = val;
    float t;
    t = __shfl_up_sync(0xffffffffu, scan, 1); if ((lane & 7) >= 1) scan += t;
    t = __shfl_up_sync(0xffffffffu, scan, 2); if ((lane & 7) >= 2) scan += t;
    t = __shfl_up_sync(0xffffffffu, scan, 4); if ((lane & 7) >= 4) scan += t;

    const int j = lane & 7;
    const float ht     = __shfl_sync(0xffffffffu, val,   8 + j);
    const float ht_inc = __shfl_sync(0xffffffffu, scan,  8 + j);
    const float sl_j   = __shfl_sync(0xffffffffu, slope, 16 + j);
    const float sl_8   = __shfl_sync(0xffffffffu, slope, 24);

    if (lane < 8) {
        const float rw = 1.f / val;
        const float lo = RMIN + scan - val;         // x_knot_j
        float4 v;
        v.x = RMIN + ht_inc - ht;                   // y_k
        v.y = ht;
        v.z = rw;
        v.w = sl_j;
        g_main[lane * DD + d] = v;
        g_c[lane * DD + d] = -lo * rw;              // xi = fma(xc, rw, c)
        if (lane < 7) g_knots[lane * DD + d] = RMIN + scan;
    }
    if (lane == 8) g_main[8 * DD + d] = make_float4(0.f, 0.f, 0.f, sl_8);

    const int g = blockIdx.x * blockDim.x + threadIdx.x;
    if (g < BB) ld_out[g] = 0.f;
}

#define DT 256        // columns per CTA (== blockDim.x)
#define NCHUNK 512    // total row-chunks of 8 (BB/8)
#define GY 74         // persistent CTAs per column group: 8*74=592 = 4/SM, one wave

__global__ void __launch_bounds__(DT, 4) eval_kernel(const float* __restrict__ x,
                                                     float* __restrict__ y,
                                                     float* __restrict__ ld_out) {
    __shared__ float4 sm4[9 * DT];   // 36.9 KB
    __shared__ float  smc[8 * DT];   //  8 KB

    const int tid = threadIdx.x;
    const int lane = tid & 31;
    const int d = blockIdx.x * DT + tid;

#pragma unroll
    for (int j = 0; j < 9; j++) sm4[j * DT + tid] = g_main[j * DD + d];
#pragma unroll
    for (int j = 0; j < 8; j++) smc[j * DT + tid] = g_c[j * DD + d];

    const float v1 = g_knots[0 * DD + d];
    const float v2 = g_knots[1 * DD + d];
    const float v3 = g_knots[2 * DD + d];
    const float v4 = g_knots[3 * DD + d];
    const float v5 = g_knots[4 * DD + d];
    const float v6 = g_knots[5 * DD + d];
    const float v7 = g_knots[6 * DD + d];
    __syncthreads();

    // lane-dependent constants for the transpose reduction
    const bool k4 = (lane & 16) != 0;
    const bool k2 = (lane & 8)  != 0;
    const bool k1 = (lane & 4)  != 0;
    const int  red_row = ((lane >> 4) & 1) * 4 + ((lane >> 3) & 1) * 2 + ((lane >> 2) & 1);

    // persistent grid-stride over row-chunks: single wave
    for (int c = blockIdx.y; c < NCHUNK; c += GY) {
        const int b0 = c * 8;
        const float* xp = x + (size_t)b0 * DD + d;
        float*       yp = y + (size_t)b0 * DD + d;

        // front-batch the 8 global loads (MLP=8)
        float xin[8];
#pragma unroll
        for (int r = 0; r < 8; r++) xin[r] = __ldg(&xp[r * DD]);

        float dv[8];
#pragma unroll
        for (int r = 0; r < 8; r++) {
            const float xv = xin[r];
            // clamp: spline eval at xc is exact at both edges (deriv = s0 / sK)
            const float xc = fminf(fmaxf(xv, RMIN), RMAX);

            // 3-level binary search
            int bin = 0;
            if (xc >= v4) bin = 4;
            const float c2 = (bin & 4) ? v6 : v2;
            if (xc >= c2) bin += 2;
            const float c1 = (bin & 4) ? ((bin & 2) ? v7 : v5)
                                       : ((bin & 2) ? v3 : v1);
            if (xc >= c1) bin += 1;

            // conflict-free gathers: LDS.128 + 2x LDS.32
            const int idx = bin * DT + tid;
            const float4 t = sm4[idx];       // {y_k, h, rw, dk}
            const float dk1 = (&sm4[idx])[DT].w;
            const float cc  = smc[idx];

            // Horner form with shared subexpressions
            const float s   = t.y * t.z;              // h / w
            const float xi  = fmaf(xc, t.z, cc);      // (xc - lo) / w
            const float sd  = s - t.w;
            const float A   = (dk1 - s) - sd;

            const float ni  = fmaf(xi, sd, t.w);
            const float t1  = fmaf(A, -xi, A);
            const float den = fmaf(xi, t1, s);
            const float rden = __fdividef(1.f, den);

            const float di  = fmaf(fmaf(A, xi, sd + sd), xi, t.w);
            const float sr  = s * rden;
            dv[r] = di * sr * sr;                     // raw derivative; log deferred

            float yv = fmaf(t.y * xi * ni, rden, t.x);

            // linear tail extension: (x - xc) is 0 in-range
            const float tail = xv - xc;
            yv = fmaf(tail, (xv < 0.f) ? t.w : dk1, yv);

            yp[r * DD] = yv;
        }

        // Transpose-reduce: stages 1-3 MULTIPLY raw derivatives (one per row held
        // per lane-group), then ONE log per 16 elements, then stages 4-5 ADD logs.
        float w4[4];
#pragma unroll
        for (int i = 0; i < 4; i++) {
            const float keep = k4 ? dv[i + 4] : dv[i];
            const float send = k4 ? dv[i] : dv[i + 4];
            w4[i] = keep * __shfl_xor_sync(0xffffffffu, send, 16);
        }
        float w2[2];
#pragma unroll
        for (int i = 0; i < 2; i++) {
            const float keep = k2 ? w4[i + 2] : w4[i];
            const float send = k2 ? w4[i] : w4[i + 2];
            w2[i] = keep * __shfl_xor_sync(0xffffffffu, send, 8);
        }
        const float pz = (k1 ? w2[1] : w2[0]) * __shfl_xor_sync(0xffffffffu, k1 ? w2[0] : w2[1], 4);

        float z = __logf(pz);           // one log per 16 elements
        z += __shfl_xor_sync(0xffffffffu, z, 2);
        z += __shfl_xor_sync(0xffffffffu, z, 1);

        if ((lane & 3) == 0) atomicAdd(&ld_out[b0 + red_row], z);
    }
}

extern "C" void kernel_launch(void* const* d_in, const int* in_sizes, int n_in,
                              void* d_out, int out_size) {
    const float* x;
    const float* params;
    if (in_sizes[0] == BB * DD) { x = (const float*)d_in[0]; params = (const float*)d_in[1]; }
    else                        { x = (const float*)d_in[1]; params = (const float*)d_in[0]; }

    float* y_out  = (float*)d_out;              // [B, D]
    float* ld_out = y_out + (size_t)BB * DD;    // [B]

    static bool configured = false;
    if (!configured) {
        cudaFuncSetAttribute(eval_kernel, cudaFuncAttributePreferredSharedMemoryCarveout, 100);
        configured = true;
    }

    norm_kernel<<<(DD * 32) / 256, 256>>>(params, ld_out);   // warp-per-d
    dim3 grid(DD / DT, GY);
    eval_kernel<<<grid, DT>>>(x, y_out, ld_out);
}